// round 1
// baseline (speedup 1.0000x reference)
#include <cuda_runtime.h>

#define Nn 8192
#define Ee 98304
#define ET (Ee + Nn)
#define Gg 64
#define INdim 128
#define Hh 8
#define Cc 128
#define HC 1024
#define TEdim 16
#define NTYPEc 32
#define NFAMc 64
#define SLOPE 0.2f
#define EPSc 1e-5f

// ---------------- scratch (device globals; no allocation allowed) ----------
__device__ float d_XL[Nn * HC];
__device__ float d_XR[Nn * HC];
__device__ float d_H1[Nn * HC];
__device__ float d_H2[Nn * HC];
__device__ int   d_rowptr[Nn + 1];
__device__ int   d_colidx[ET];
__device__ int   d_cnt[Nn];
__device__ int   d_cur[Nn];
__device__ float d_gsum[Gg * HC];
__device__ int   d_gcnt[Gg];

// ---------------- CSR build ------------------------------------------------
__global__ void csr_zero_kernel() {
    int i = blockIdx.x * blockDim.x + threadIdx.x;
    if (i < Nn) { d_cnt[i] = 0; d_cur[i] = 0; }
}

__global__ void csr_count_kernel(const int* __restrict__ edge) {
    int i = blockIdx.x * blockDim.x + threadIdx.x;
    if (i < ET) {
        int dst = (i < Ee) ? edge[Ee + i] : (i - Ee);
        atomicAdd(&d_cnt[dst], 1);
    }
}

__global__ void csr_scan_kernel() {
    // one block of 1024 threads, 8 counters each
    int tid = threadIdx.x;
    int base = tid * 8;
    int local[8];
    int s = 0;
#pragma unroll
    for (int j = 0; j < 8; j++) { local[j] = d_cnt[base + j]; s += local[j]; }
    __shared__ int ps[1024];
    ps[tid] = s;
    __syncthreads();
    for (int off = 1; off < 1024; off <<= 1) {
        int v = (tid >= off) ? ps[tid - off] : 0;
        __syncthreads();
        ps[tid] += v;
        __syncthreads();
    }
    int run = ps[tid] - s;  // exclusive prefix of this thread's chunk
#pragma unroll
    for (int j = 0; j < 8; j++) { d_rowptr[base + j] = run; run += local[j]; }
    if (tid == 1023) d_rowptr[Nn] = run;
}

__global__ void csr_fill_kernel(const int* __restrict__ edge) {
    int i = blockIdx.x * blockDim.x + threadIdx.x;
    if (i < ET) {
        int src, dst;
        if (i < Ee) { src = edge[i]; dst = edge[Ee + i]; }
        else        { src = i - Ee;  dst = i - Ee; }
        int pos = d_rowptr[dst] + atomicAdd(&d_cur[dst], 1);
        d_colidx[pos] = src;
    }
}

// ---------------- SGEMM: [8192 x K] @ [K x 1024] + bias --------------------
// BM=BN=128, BK=16, 256 threads, 8x8 micro-tile.
__global__ __launch_bounds__(256, 2) void sgemm_bias_kernel(
    const float* __restrict__ Aext, const float* __restrict__ B,
    const float* __restrict__ bias, int a_sel, int out_sel, int K) {
    const float* A = (a_sel == 0) ? Aext : ((a_sel == 1) ? d_H1 : d_H2);
    float* Cm = (out_sel == 0) ? d_XL : d_XR;

    __shared__ float As[16][128];
    __shared__ float Bs[16][128];

    int tid  = threadIdx.x;
    int row0 = blockIdx.y * 128;
    int col0 = blockIdx.x * 128;

    int arow = tid >> 1;          // 0..127
    int ak   = (tid & 1) * 8;     // 0 or 8
    int brow = tid >> 4;          // 0..15
    int bcol = (tid & 15) * 8;    // 0..120
    int tr   = tid >> 4;          // 0..15
    int tc   = tid & 15;          // 0..15

    float acc[8][8];
#pragma unroll
    for (int i = 0; i < 8; i++)
#pragma unroll
        for (int j = 0; j < 8; j++) acc[i][j] = 0.f;

    for (int k0 = 0; k0 < K; k0 += 16) {
        float4 a0 = *(const float4*)&A[(size_t)(row0 + arow) * K + k0 + ak];
        float4 a1 = *(const float4*)&A[(size_t)(row0 + arow) * K + k0 + ak + 4];
        As[ak + 0][arow] = a0.x; As[ak + 1][arow] = a0.y;
        As[ak + 2][arow] = a0.z; As[ak + 3][arow] = a0.w;
        As[ak + 4][arow] = a1.x; As[ak + 5][arow] = a1.y;
        As[ak + 6][arow] = a1.z; As[ak + 7][arow] = a1.w;
        float4 b0 = *(const float4*)&B[(size_t)(k0 + brow) * HC + col0 + bcol];
        float4 b1 = *(const float4*)&B[(size_t)(k0 + brow) * HC + col0 + bcol + 4];
        *(float4*)&Bs[brow][bcol]     = b0;
        *(float4*)&Bs[brow][bcol + 4] = b1;
        __syncthreads();

#pragma unroll
        for (int k = 0; k < 16; k++) {
            float a[8], bv[8];
            *(float4*)(a)      = *(float4*)&As[k][tr * 8];
            *(float4*)(a + 4)  = *(float4*)&As[k][tr * 8 + 4];
            *(float4*)(bv)     = *(float4*)&Bs[k][tc * 8];
            *(float4*)(bv + 4) = *(float4*)&Bs[k][tc * 8 + 4];
#pragma unroll
            for (int i = 0; i < 8; i++)
#pragma unroll
                for (int j = 0; j < 8; j++) acc[i][j] = fmaf(a[i], bv[j], acc[i][j]);
        }
        __syncthreads();
    }

#pragma unroll
    for (int i = 0; i < 8; i++) {
        int row = row0 + tr * 8 + i;
        int col = col0 + tc * 8;
        float4 o0, o1;
        o0.x = acc[i][0] + bias[col + 0];
        o0.y = acc[i][1] + bias[col + 1];
        o0.z = acc[i][2] + bias[col + 2];
        o0.w = acc[i][3] + bias[col + 3];
        o1.x = acc[i][4] + bias[col + 4];
        o1.y = acc[i][5] + bias[col + 5];
        o1.z = acc[i][6] + bias[col + 6];
        o1.w = acc[i][7] + bias[col + 7];
        *(float4*)&Cm[(size_t)row * HC + col]     = o0;
        *(float4*)&Cm[(size_t)row * HC + col + 4] = o1;
    }
}

// ---------------- GATv2 aggregation + bias + ReLU + LayerNorm (+res) ------
// block = 256 threads = 8 warps, one warp per head; one block per dst node.
// Online softmax, xl[src] rows read exactly once, all state in registers.
__global__ __launch_bounds__(256) void gat_edge_kernel(
    const float* __restrict__ att, const float* __restrict__ bias,
    const float* __restrict__ lng, const float* __restrict__ lnb,
    int res_sel, int out_sel) {
    int n = blockIdx.x;
    int w = threadIdx.x >> 5;
    int l = threadIdx.x & 31;
    int c0 = w * Cc + l;

    const float* xr = d_XR + (size_t)n * HC;
    float xr0 = xr[c0], xr1 = xr[c0 + 32], xr2 = xr[c0 + 64], xr3 = xr[c0 + 96];
    const float* ah = att + w * Cc;
    float a0 = ah[l], a1 = ah[l + 32], a2 = ah[l + 64], a3 = ah[l + 96];

    float m = -3.0e38f, dsum = 0.f;
    float acc0 = 0.f, acc1 = 0.f, acc2 = 0.f, acc3 = 0.f;

    int beg = d_rowptr[n], end = d_rowptr[n + 1];
    for (int e = beg; e < end; e++) {
        int s = d_colidx[e];
        const float* xl = d_XL + (size_t)s * HC;
        float x0 = xl[c0], x1 = xl[c0 + 32], x2 = xl[c0 + 64], x3 = xl[c0 + 96];
        float t0 = x0 + xr0; t0 = (t0 > 0.f) ? t0 : SLOPE * t0;
        float t1 = x1 + xr1; t1 = (t1 > 0.f) ? t1 : SLOPE * t1;
        float t2 = x2 + xr2; t2 = (t2 > 0.f) ? t2 : SLOPE * t2;
        float t3 = x3 + xr3; t3 = (t3 > 0.f) ? t3 : SLOPE * t3;
        float p = a0 * t0 + a1 * t1 + a2 * t2 + a3 * t3;
#pragma unroll
        for (int off = 16; off; off >>= 1) p += __shfl_xor_sync(0xffffffffu, p, off);
        float mn = fmaxf(m, p);
        float sc = __expf(m - mn);
        float wg = __expf(p - mn);
        dsum = dsum * sc + wg;
        acc0 = acc0 * sc + x0 * wg;
        acc1 = acc1 * sc + x1 * wg;
        acc2 = acc2 * sc + x2 * wg;
        acc3 = acc3 * sc + x3 * wg;
        m = mn;
    }

    float inv = 1.f / dsum;
    float v0 = fmaxf(acc0 * inv + bias[c0],       0.f);
    float v1 = fmaxf(acc1 * inv + bias[c0 + 32],  0.f);
    float v2 = fmaxf(acc2 * inv + bias[c0 + 64],  0.f);
    float v3 = fmaxf(acc3 * inv + bias[c0 + 96],  0.f);

    // block mean / var over 1024 channels
    float ps = v0 + v1 + v2 + v3;
    float pq = v0 * v0 + v1 * v1 + v2 * v2 + v3 * v3;
#pragma unroll
    for (int off = 16; off; off >>= 1) {
        ps += __shfl_xor_sync(0xffffffffu, ps, off);
        pq += __shfl_xor_sync(0xffffffffu, pq, off);
    }
    __shared__ float rs[8], rq[8];
    __shared__ float s_mu, s_rstd;
    if (l == 0) { rs[w] = ps; rq[w] = pq; }
    __syncthreads();
    if (threadIdx.x == 0) {
        float S = 0.f, Q = 0.f;
#pragma unroll
        for (int k = 0; k < 8; k++) { S += rs[k]; Q += rq[k]; }
        float mu = S * (1.f / HC);
        float var = Q * (1.f / HC) - mu * mu;
        s_mu = mu;
        s_rstd = rsqrtf(var + EPSc);
    }
    __syncthreads();
    float mu = s_mu, rstd = s_rstd;

    const float* res = (res_sel == 0) ? nullptr : ((res_sel == 1) ? d_H1 : d_H2);
    float* Ho = (out_sel == 1) ? d_H1 : d_H2;
    size_t o = (size_t)n * HC;
    float r0 = res ? res[o + c0]      : 0.f;
    float r1 = res ? res[o + c0 + 32] : 0.f;
    float r2 = res ? res[o + c0 + 64] : 0.f;
    float r3 = res ? res[o + c0 + 96] : 0.f;
    Ho[o + c0]      = (v0 - mu) * rstd * lng[c0]      + lnb[c0]      + r0;
    Ho[o + c0 + 32] = (v1 - mu) * rstd * lng[c0 + 32] + lnb[c0 + 32] + r1;
    Ho[o + c0 + 64] = (v2 - mu) * rstd * lng[c0 + 64] + lnb[c0 + 64] + r2;
    Ho[o + c0 + 96] = (v3 - mu) * rstd * lng[c0 + 96] + lnb[c0 + 96] + r3;
}

// ---------------- pooling + heads ------------------------------------------
__global__ void pool_zero_kernel() {
    int i = blockIdx.x * blockDim.x + threadIdx.x;
    if (i < Gg * HC) d_gsum[i] = 0.f;
    if (i < Gg) d_gcnt[i] = 0;
}

__global__ void pool_sum_kernel(const int* __restrict__ batch) {
    int i = blockIdx.x * blockDim.x + threadIdx.x;
    if (i < Nn * HC) {
        int nIdx = i >> 10;
        int c = i & (HC - 1);
        atomicAdd(&d_gsum[batch[nIdx] * HC + c], d_H2[i]);
    }
}

__global__ void pool_cnt_kernel(const int* __restrict__ batch) {
    int i = blockIdx.x * blockDim.x + threadIdx.x;
    if (i < Nn) atomicAdd(&d_gcnt[batch[i]], 1);
}

__global__ void head_kernel(const int* __restrict__ y_type,
                            const float* __restrict__ Temb,
                            const float* __restrict__ W_fam,
                            const float* __restrict__ b_fam,
                            const float* __restrict__ W_type,
                            const float* __restrict__ b_type,
                            float* __restrict__ out) {
    __shared__ float gf[HC + TEdim];
    int g = blockIdx.x;
    int tid = threadIdx.x;
    float cnt = fmaxf((float)d_gcnt[g], 1.f);
    float invc = 1.f / cnt;
    for (int c = tid; c < HC; c += 128) gf[c] = d_gsum[g * HC + c] * invc;
    if (tid < TEdim) gf[HC + tid] = Temb[y_type[g] * TEdim + tid];
    __syncthreads();
    if (tid < NFAMc) {
        float s = b_fam[tid];
        for (int c = 0; c < HC + TEdim; c++) s += gf[c] * W_fam[c * NFAMc + tid];
        out[g * NFAMc + tid] = s;
    } else if (tid < NFAMc + NTYPEc) {
        int j = tid - NFAMc;
        float s = b_type[j];
        for (int c = 0; c < HC + TEdim; c++) s += gf[c] * W_type[c * NTYPEc + j];
        out[Gg * NFAMc + g * NTYPEc + j] = s;
    }
}

// ---------------- launch ----------------------------------------------------
extern "C" void kernel_launch(void* const* d_in, const int* in_sizes, int n_in,
                              void* d_out, int out_size) {
    const float* x      = (const float*)d_in[0];
    const int*   edge   = (const int*)d_in[1];
    const int*   batch  = (const int*)d_in[2];
    const int*   y_type = (const int*)d_in[3];
    const float* Wl0    = (const float*)d_in[4];
    const float* bl0    = (const float*)d_in[5];
    const float* Wr0    = (const float*)d_in[6];
    const float* br0    = (const float*)d_in[7];
    const float* att0   = (const float*)d_in[8];
    const float* b0     = (const float*)d_in[9];
    const float* Wl     = (const float*)d_in[10];
    const float* bl     = (const float*)d_in[11];
    const float* Wr     = (const float*)d_in[12];
    const float* br     = (const float*)d_in[13];
    const float* att    = (const float*)d_in[14];
    const float* b      = (const float*)d_in[15];
    const float* ln_g   = (const float*)d_in[16];
    const float* ln_b   = (const float*)d_in[17];
    const float* Temb   = (const float*)d_in[18];
    const float* W_fam  = (const float*)d_in[19];
    const float* b_fam  = (const float*)d_in[20];
    const float* W_type = (const float*)d_in[21];
    const float* b_type = (const float*)d_in[22];
    float* out = (float*)d_out;

    // CSR build (per launch; deterministic up to fp-summation order)
    csr_zero_kernel<<<(Nn + 255) / 256, 256>>>();
    csr_count_kernel<<<(ET + 255) / 256, 256>>>(edge);
    csr_scan_kernel<<<1, 1024>>>();
    csr_fill_kernel<<<(ET + 255) / 256, 256>>>(edge);

    dim3 gg(HC / 128, Nn / 128);

    // layer 0 (in_dim 128 -> 1024), no residual, output -> H1
    sgemm_bias_kernel<<<gg, 256>>>(x, Wl0, bl0, 0, 0, INdim);
    sgemm_bias_kernel<<<gg, 256>>>(x, Wr0, br0, 0, 1, INdim);
    gat_edge_kernel<<<Nn, 256>>>(att0, b0, ln_g, ln_b, 0, 1);

    // layers 1..3: residual + LN, alternate H1 <-> H2
    for (int i = 0; i < 3; i++) {
        int insel = (i & 1) ? 2 : 1;      // i=0: H1, i=1: H2, i=2: H1
        int outsel = (i & 1) ? 1 : 2;     // i=0: H2, i=1: H1, i=2: H2
        const float* Wli = Wl + (size_t)i * HC * HC;
        const float* Wri = Wr + (size_t)i * HC * HC;
        sgemm_bias_kernel<<<gg, 256>>>(nullptr, Wli, bl + i * HC, insel, 0, HC);
        sgemm_bias_kernel<<<gg, 256>>>(nullptr, Wri, br + i * HC, insel, 1, HC);
        gat_edge_kernel<<<Nn, 256>>>(att + (size_t)i * Hh * Cc, b + i * HC,
                                     ln_g + (i + 1) * HC, ln_b + (i + 1) * HC,
                                     insel, outsel);
    }

    // mean pool + heads (final hidden state is H2)
    pool_zero_kernel<<<(Gg * HC + 255) / 256, 256>>>();
    pool_sum_kernel<<<(Nn * HC + 255) / 256, 256>>>(batch);
    pool_cnt_kernel<<<(Nn + 255) / 256, 256>>>(batch);
    head_kernel<<<Gg, 128>>>(y_type, Temb, W_fam, b_fam, W_type, b_type, out);
}

// round 5
// speedup vs baseline: 1.9824x; 1.9824x over previous
#include <cuda_runtime.h>
#include <cuda_bf16.h>
#include <cstdint>

#define Nn 8192
#define Ee 98304
#define ET (Ee + Nn)
#define Gg 64
#define INdim 128
#define Hh 8
#define Cc 128
#define HC 1024
#define TEdim 16
#define NTYPEc 32
#define NFAMc 64
#define SLOPE 0.2f
#define EPSc 1e-5f

// ---- GEMM tiling (mma.sync bf16, split-fp32 via K-concat x3) ---------------
#define BM 128
#define BN 128
#define BKc 32
#define ROWB 80                 // padded SMEM row stride in bytes (32 bf16 = 64B data)
#define STG 20480               // per-stage bytes: A 128*80 + B 128*80
#define NSTAGE 3
#define GEMM_SMEM (NSTAGE * STG)

// d_Wcat element offsets ([n][3K] bf16 per matrix)
#define BIGW 3145728            // 1024*3072
#define SMALLW 393216           // 1024*384
#define OFF_WL0 0
#define OFF_WR0 SMALLW
#define OFF_WB (2 * SMALLW)
#define OFF_WLi(i) (OFF_WB + (size_t)(i) * 2 * BIGW)
#define OFF_WRi(i) (OFF_WLi(i) + BIGW)
#define WT_ELEMS (OFF_WB + 6 * BIGW)
#define ACAT_ELEMS (Nn * 3072)

// ---------------- scratch (device globals; no allocation allowed) ----------
__device__ float d_XL[Nn * HC];
__device__ float d_XR[Nn * HC];
__device__ float d_H1[Nn * HC];
__device__ float d_H2[Nn * HC];
__device__ int   d_rowptr[Nn + 1];
__device__ int   d_colidx[ET];
__device__ int   d_cnt[Nn];
__device__ int   d_cur[Nn];
__device__ float d_gsum[Gg * HC];
__device__ int   d_gcnt[Gg];
__device__ __nv_bfloat16 d_Acat[ACAT_ELEMS];
__device__ __nv_bfloat16 d_Wcat[WT_ELEMS];

// ---------------- PTX helpers ----------------------------------------------
__device__ __forceinline__ uint32_t smem_u32_of(const void* p) {
    uint32_t a;
    asm("{ .reg .u64 t; cvta.to.shared.u64 t, %1; cvt.u32.u64 %0, t; }" : "=r"(a) : "l"(p));
    return a;
}

#define CPA16(dst, src) \
    asm volatile("cp.async.cg.shared.global [%0], [%1], 16;" :: "r"(dst), "l"(src))

#define LDSMX4(r, addr) \
    asm volatile("ldmatrix.sync.aligned.m8n8.x4.shared.b16 {%0,%1,%2,%3}, [%4];" \
                 : "=r"((r)[0]), "=r"((r)[1]), "=r"((r)[2]), "=r"((r)[3]) : "r"(addr))

#define MMA16816(c, a, b0, b1) \
    asm volatile("mma.sync.aligned.m16n8k16.row.col.f32.bf16.bf16.f32 " \
                 "{%0,%1,%2,%3}, {%4,%5,%6,%7}, {%8,%9}, {%0,%1,%2,%3};" \
                 : "+f"((c)[0]), "+f"((c)[1]), "+f"((c)[2]), "+f"((c)[3]) \
                 : "r"((a)[0]), "r"((a)[1]), "r"((a)[2]), "r"((a)[3]), "r"(b0), "r"(b1))

// ---------------- CSR build ------------------------------------------------
__global__ void csr_zero_kernel() {
    int i = blockIdx.x * blockDim.x + threadIdx.x;
    if (i < Nn) { d_cnt[i] = 0; d_cur[i] = 0; }
}

__global__ void csr_count_kernel(const int* __restrict__ edge) {
    int i = blockIdx.x * blockDim.x + threadIdx.x;
    if (i < ET) {
        int dst = (i < Ee) ? edge[Ee + i] : (i - Ee);
        atomicAdd(&d_cnt[dst], 1);
    }
}

__global__ void csr_scan_kernel() {
    int tid = threadIdx.x;
    int base = tid * 8;
    int local[8];
    int s = 0;
#pragma unroll
    for (int j = 0; j < 8; j++) { local[j] = d_cnt[base + j]; s += local[j]; }
    __shared__ int ps[1024];
    ps[tid] = s;
    __syncthreads();
    for (int off = 1; off < 1024; off <<= 1) {
        int v = (tid >= off) ? ps[tid - off] : 0;
        __syncthreads();
        ps[tid] += v;
        __syncthreads();
    }
    int run = ps[tid] - s;
#pragma unroll
    for (int j = 0; j < 8; j++) { d_rowptr[base + j] = run; run += local[j]; }
    if (tid == 1023) d_rowptr[Nn] = run;
}

__global__ void csr_fill_kernel(const int* __restrict__ edge) {
    int i = blockIdx.x * blockDim.x + threadIdx.x;
    if (i < ET) {
        int src, dst;
        if (i < Ee) { src = edge[i]; dst = edge[Ee + i]; }
        else        { src = i - Ee;  dst = i - Ee; }
        int pos = d_rowptr[dst] + atomicAdd(&d_cur[dst], 1);
        d_colidx[pos] = src;
    }
}

// ---------------- fp32 -> split bf16, K-concat [hi | hi | lo] ---------------
__global__ void convA_kernel(const float* __restrict__ ext, int sel, int kshift) {
    int i = blockIdx.x * blockDim.x + threadIdx.x;
    int K = 1 << kshift;
    if (i < (Nn << kshift)) {
        const float* s = (sel == 0) ? ext : ((sel == 1) ? d_H1 : d_H2);
        float v = s[i];
        __nv_bfloat16 h = __float2bfloat16(v);
        __nv_bfloat16 lo = __float2bfloat16(v - __bfloat162float(h));
        int r = i >> kshift;
        int k = i & (K - 1);
        size_t o = (size_t)r * (3 * K) + k;
        d_Acat[o] = h;
        d_Acat[o + K] = h;
        d_Acat[o + 2 * K] = lo;
    }
}

// transpose [K,1024] -> [1024,3K] with [Bh | Bl | Bh] concat
__global__ void convW_kernel(const float* __restrict__ W, size_t outOff, int K) {
    __shared__ float t[32][33];
    int k0 = blockIdx.x * 32, n0 = blockIdx.y * 32;
    int tx = threadIdx.x, ty = threadIdx.y;
    for (int r = ty; r < 32; r += 8) t[r][tx] = W[(size_t)(k0 + r) * HC + n0 + tx];
    __syncthreads();
    for (int r = ty; r < 32; r += 8) {
        float v = t[tx][r];  // = W[k0+tx][n0+r]
        __nv_bfloat16 h = __float2bfloat16(v);
        __nv_bfloat16 lo = __float2bfloat16(v - __bfloat162float(h));
        size_t o = outOff + (size_t)(n0 + r) * (3 * K) + (k0 + tx);
        d_Wcat[o] = h;          // pairs with Ah
        d_Wcat[o + K] = lo;     // pairs with Ah
        d_Wcat[o + 2 * K] = h;  // pairs with Al
    }
}

// ---------------- mma.sync GEMM: C[8192x1024] = Acat @ Wcat^T + bias --------
// CTA 128x128, BK=32, 3-stage cp.async pipeline, warp grid 2(m) x 4(n).
__global__ __launch_bounds__(256) void gemm_mma_kernel(
    size_t wOff, const float* __restrict__ bias, int out_sel, int K3) {
    extern __shared__ __align__(128) char sm[];
    uint32_t su = smem_u32_of(sm);
    const __nv_bfloat16* __restrict__ Ag = d_Acat;
    const __nv_bfloat16* __restrict__ Bg = d_Wcat + wOff;
    float* __restrict__ Cm = out_sel ? d_XR : d_XL;

    int tid = threadIdx.x;
    int wid = tid >> 5, l = tid & 31;
    int wm = wid >> 2, wn = wid & 3;
    int row0 = blockIdx.y * BM, col0 = blockIdx.x * BN;

    // cp.async task: thread covers rows (tid>>2) and (tid>>2)+64, chunk tid&3
    int lr = tid >> 2;
    int chB = (tid & 3) * 16;   // smem byte offset of 16B chunk
    int ch8 = (tid & 3) * 8;    // gmem element offset

    // ldmatrix per-lane bases (byte offsets within a stage)
    uint32_t aOff = (uint32_t)((wm * 64 + (l & 15)) * ROWB + (l >> 4) * 16);
    uint32_t bOff = (uint32_t)(BM * ROWB +
                               (wn * 32 + (l & 7) + ((l >> 4) << 3)) * ROWB +
                               ((l >> 3) & 1) * 16);

    float c[4][4][4];
#pragma unroll
    for (int a = 0; a < 4; a++)
#pragma unroll
        for (int b = 0; b < 4; b++)
#pragma unroll
            for (int d = 0; d < 4; d++) c[a][b][d] = 0.f;

    const int NT = K3 >> 5;

    // prologue: stages 0,1
#pragma unroll
    for (int s = 0; s < NSTAGE - 1; s++) {
        uint32_t sb = su + s * STG;
        int k0 = s * BKc;
        CPA16(sb + lr * ROWB + chB,               Ag + (size_t)(row0 + lr) * K3 + k0 + ch8);
        CPA16(sb + (lr + 64) * ROWB + chB,        Ag + (size_t)(row0 + lr + 64) * K3 + k0 + ch8);
        CPA16(sb + BM * ROWB + lr * ROWB + chB,        Bg + (size_t)(col0 + lr) * K3 + k0 + ch8);
        CPA16(sb + BM * ROWB + (lr + 64) * ROWB + chB, Bg + (size_t)(col0 + lr + 64) * K3 + k0 + ch8);
        asm volatile("cp.async.commit_group;" ::: "memory");
    }

    for (int it = 0; it < NT; it++) {
        asm volatile("cp.async.wait_group %0;" :: "n"(NSTAGE - 2) : "memory");
        __syncthreads();

        uint32_t sb = su + (it % NSTAGE) * STG;
#pragma unroll
        for (int kk = 0; kk < 2; kk++) {
            uint32_t av[4][4], bv[2][4];
#pragma unroll
            for (int mt = 0; mt < 4; mt++)
                LDSMX4(av[mt], sb + aOff + mt * (16 * ROWB) + kk * 32);
#pragma unroll
            for (int bt = 0; bt < 2; bt++)
                LDSMX4(bv[bt], sb + bOff + bt * (16 * ROWB) + kk * 32);
#pragma unroll
            for (int mt = 0; mt < 4; mt++) {
                MMA16816(c[mt][0], av[mt], bv[0][0], bv[0][1]);
                MMA16816(c[mt][1], av[mt], bv[0][2], bv[0][3]);
                MMA16816(c[mt][2], av[mt], bv[1][0], bv[1][1]);
                MMA16816(c[mt][3], av[mt], bv[1][2], bv[1][3]);
            }
        }

        // load stage (it + NSTAGE - 1): overwrites stage computed at it-1
        int kn = (it + NSTAGE - 1) * BKc;
        if (kn < K3) {
            uint32_t sb2 = su + ((it + NSTAGE - 1) % NSTAGE) * STG;
            CPA16(sb2 + lr * ROWB + chB,               Ag + (size_t)(row0 + lr) * K3 + kn + ch8);
            CPA16(sb2 + (lr + 64) * ROWB + chB,        Ag + (size_t)(row0 + lr + 64) * K3 + kn + ch8);
            CPA16(sb2 + BM * ROWB + lr * ROWB + chB,        Bg + (size_t)(col0 + lr) * K3 + kn + ch8);
            CPA16(sb2 + BM * ROWB + (lr + 64) * ROWB + chB, Bg + (size_t)(col0 + lr + 64) * K3 + kn + ch8);
        }
        asm volatile("cp.async.commit_group;" ::: "memory");
    }

    // epilogue: c[mt][nt] -> rows (wm*64+mt*16+l/4, +8), cols (wn*32+nt*8+(l%4)*2)
    int mrow = l >> 2;
    int ncol = (l & 3) * 2;
#pragma unroll
    for (int mt = 0; mt < 4; mt++) {
#pragma unroll
        for (int nt = 0; nt < 4; nt++) {
            int row = row0 + wm * 64 + mt * 16 + mrow;
            int col = col0 + wn * 32 + nt * 8 + ncol;
            float b0 = bias[col], b1 = bias[col + 1];
            float2 v0 = make_float2(c[mt][nt][0] + b0, c[mt][nt][1] + b1);
            float2 v1 = make_float2(c[mt][nt][2] + b0, c[mt][nt][3] + b1);
            *(float2*)&Cm[(size_t)row * HC + col] = v0;
            *(float2*)&Cm[(size_t)(row + 8) * HC + col] = v1;
        }
    }
}

// ---------------- GATv2 aggregation + bias + ReLU + LayerNorm (+res) ------
__global__ __launch_bounds__(256) void gat_edge_kernel(
    const float* __restrict__ att, const float* __restrict__ bias,
    const float* __restrict__ lng, const float* __restrict__ lnb,
    int res_sel, int out_sel) {
    int n = blockIdx.x;
    int w = threadIdx.x >> 5;
    int l = threadIdx.x & 31;
    int c0 = w * Cc + l;

    const float* xr = d_XR + (size_t)n * HC;
    float xr0 = xr[c0], xr1 = xr[c0 + 32], xr2 = xr[c0 + 64], xr3 = xr[c0 + 96];
    const float* ah = att + w * Cc;
    float a0 = ah[l], a1 = ah[l + 32], a2 = ah[l + 64], a3 = ah[l + 96];

    float m = -3.0e38f, dsum = 0.f;
    float acc0 = 0.f, acc1 = 0.f, acc2 = 0.f, acc3 = 0.f;

    int beg = d_rowptr[n], end = d_rowptr[n + 1];
    for (int e = beg; e < end; e++) {
        int s = d_colidx[e];
        const float* xl = d_XL + (size_t)s * HC;
        float x0 = xl[c0], x1 = xl[c0 + 32], x2 = xl[c0 + 64], x3 = xl[c0 + 96];
        float t0 = x0 + xr0; t0 = (t0 > 0.f) ? t0 : SLOPE * t0;
        float t1 = x1 + xr1; t1 = (t1 > 0.f) ? t1 : SLOPE * t1;
        float t2 = x2 + xr2; t2 = (t2 > 0.f) ? t2 : SLOPE * t2;
        float t3 = x3 + xr3; t3 = (t3 > 0.f) ? t3 : SLOPE * t3;
        float p = a0 * t0 + a1 * t1 + a2 * t2 + a3 * t3;
#pragma unroll
        for (int off = 16; off; off >>= 1) p += __shfl_xor_sync(0xffffffffu, p, off);
        float mn = fmaxf(m, p);
        float sc = __expf(m - mn);
        float wg = __expf(p - mn);
        dsum = dsum * sc + wg;
        acc0 = acc0 * sc + x0 * wg;
        acc1 = acc1 * sc + x1 * wg;
        acc2 = acc2 * sc + x2 * wg;
        acc3 = acc3 * sc + x3 * wg;
        m = mn;
    }

    float inv = 1.f / dsum;
    float v0 = fmaxf(acc0 * inv + bias[c0],       0.f);
    float v1 = fmaxf(acc1 * inv + bias[c0 + 32],  0.f);
    float v2 = fmaxf(acc2 * inv + bias[c0 + 64],  0.f);
    float v3 = fmaxf(acc3 * inv + bias[c0 + 96],  0.f);

    float ps = v0 + v1 + v2 + v3;
    float pq = v0 * v0 + v1 * v1 + v2 * v2 + v3 * v3;
#pragma unroll
    for (int off = 16; off; off >>= 1) {
        ps += __shfl_xor_sync(0xffffffffu, ps, off);
        pq += __shfl_xor_sync(0xffffffffu, pq, off);
    }
    __shared__ float rs[8], rq[8];
    __shared__ float s_mu, s_rstd;
    if (l == 0) { rs[w] = ps; rq[w] = pq; }
    __syncthreads();
    if (threadIdx.x == 0) {
        float S = 0.f, Q = 0.f;
#pragma unroll
        for (int k = 0; k < 8; k++) { S += rs[k]; Q += rq[k]; }
        float mu = S * (1.f / HC);
        float var = Q * (1.f / HC) - mu * mu;
        s_mu = mu;
        s_rstd = rsqrtf(var + EPSc);
    }
    __syncthreads();
    float mu = s_mu, rstd = s_rstd;

    const float* res = (res_sel == 0) ? nullptr : ((res_sel == 1) ? d_H1 : d_H2);
    float* Ho = (out_sel == 1) ? d_H1 : d_H2;
    size_t o = (size_t)n * HC;
    float r0 = res ? res[o + c0]      : 0.f;
    float r1 = res ? res[o + c0 + 32] : 0.f;
    float r2 = res ? res[o + c0 + 64] : 0.f;
    float r3 = res ? res[o + c0 + 96] : 0.f;
    Ho[o + c0]      = (v0 - mu) * rstd * lng[c0]      + lnb[c0]      + r0;
    Ho[o + c0 + 32] = (v1 - mu) * rstd * lng[c0 + 32] + lnb[c0 + 32] + r1;
    Ho[o + c0 + 64] = (v2 - mu) * rstd * lng[c0 + 64] + lnb[c0 + 64] + r2;
    Ho[o + c0 + 96] = (v3 - mu) * rstd * lng[c0 + 96] + lnb[c0 + 96] + r3;
}

// ---------------- pooling + heads ------------------------------------------
__global__ void pool_zero_kernel() {
    int i = blockIdx.x * blockDim.x + threadIdx.x;
    if (i < Gg * HC) d_gsum[i] = 0.f;
    if (i < Gg) d_gcnt[i] = 0;
}

__global__ void pool_sum_kernel(const int* __restrict__ batch) {
    int i = blockIdx.x * blockDim.x + threadIdx.x;
    if (i < Nn * HC) {
        int nIdx = i >> 10;
        int c = i & (HC - 1);
        atomicAdd(&d_gsum[batch[nIdx] * HC + c], d_H2[i]);
    }
}

__global__ void pool_cnt_kernel(const int* __restrict__ batch) {
    int i = blockIdx.x * blockDim.x + threadIdx.x;
    if (i < Nn) atomicAdd(&d_gcnt[batch[i]], 1);
}

__global__ void head_kernel(const int* __restrict__ y_type,
                            const float* __restrict__ Temb,
                            const float* __restrict__ W_fam,
                            const float* __restrict__ b_fam,
                            const float* __restrict__ W_type,
                            const float* __restrict__ b_type,
                            float* __restrict__ out) {
    __shared__ float gf[HC + TEdim];
    int g = blockIdx.x;
    int tid = threadIdx.x;
    float cnt = fmaxf((float)d_gcnt[g], 1.f);
    float invc = 1.f / cnt;
    for (int c = tid; c < HC; c += 128) gf[c] = d_gsum[g * HC + c] * invc;
    if (tid < TEdim) gf[HC + tid] = Temb[y_type[g] * TEdim + tid];
    __syncthreads();
    if (tid < NFAMc) {
        float s = b_fam[tid];
        for (int c = 0; c < HC + TEdim; c++) s += gf[c] * W_fam[c * NFAMc + tid];
        out[g * NFAMc + tid] = s;
    } else if (tid < NFAMc + NTYPEc) {
        int j = tid - NFAMc;
        float s = b_type[j];
        for (int c = 0; c < HC + TEdim; c++) s += gf[c] * W_type[c * NTYPEc + j];
        out[Gg * NFAMc + g * NTYPEc + j] = s;
    }
}

// ---------------- launch ----------------------------------------------------
extern "C" void kernel_launch(void* const* d_in, const int* in_sizes, int n_in,
                              void* d_out, int out_size) {
    const float* x      = (const float*)d_in[0];
    const int*   edge   = (const int*)d_in[1];
    const int*   batch  = (const int*)d_in[2];
    const int*   y_type = (const int*)d_in[3];
    const float* Wl0    = (const float*)d_in[4];
    const float* bl0    = (const float*)d_in[5];
    const float* Wr0    = (const float*)d_in[6];
    const float* br0    = (const float*)d_in[7];
    const float* att0   = (const float*)d_in[8];
    const float* b0     = (const float*)d_in[9];
    const float* Wl     = (const float*)d_in[10];
    const float* bl     = (const float*)d_in[11];
    const float* Wr     = (const float*)d_in[12];
    const float* br     = (const float*)d_in[13];
    const float* att    = (const float*)d_in[14];
    const float* b      = (const float*)d_in[15];
    const float* ln_g   = (const float*)d_in[16];
    const float* ln_b   = (const float*)d_in[17];
    const float* Temb   = (const float*)d_in[18];
    const float* W_fam  = (const float*)d_in[19];
    const float* b_fam  = (const float*)d_in[20];
    const float* W_type = (const float*)d_in[21];
    const float* b_type = (const float*)d_in[22];
    float* out = (float*)d_out;

    cudaFuncSetAttribute(gemm_mma_kernel,
                         cudaFuncAttributeMaxDynamicSharedMemorySize, GEMM_SMEM);

    // weight transpose + split + concat (per launch)
    dim3 wtb(32, 8);
    convW_kernel<<<dim3(4, 32), wtb>>>(Wl0, OFF_WL0, INdim);
    convW_kernel<<<dim3(4, 32), wtb>>>(Wr0, OFF_WR0, INdim);
    for (int i = 0; i < 3; i++) {
        convW_kernel<<<dim3(32, 32), wtb>>>(Wl + (size_t)i * HC * HC, OFF_WLi(i), HC);
        convW_kernel<<<dim3(32, 32), wtb>>>(Wr + (size_t)i * HC * HC, OFF_WRi(i), HC);
    }

    // CSR build
    csr_zero_kernel<<<(Nn + 255) / 256, 256>>>();
    csr_count_kernel<<<(ET + 255) / 256, 256>>>(edge);
    csr_scan_kernel<<<1, 1024>>>();
    csr_fill_kernel<<<(ET + 255) / 256, 256>>>(edge);

    dim3 gg(HC / BN, Nn / BM);  // (8, 64)

    // layer 0 (K=128 -> K3=384)
    convA_kernel<<<(Nn * INdim + 255) / 256, 256>>>(x, 0, 7);
    gemm_mma_kernel<<<gg, 256, GEMM_SMEM>>>(OFF_WL0, bl0, 0, 3 * INdim);
    gemm_mma_kernel<<<gg, 256, GEMM_SMEM>>>(OFF_WR0, br0, 1, 3 * INdim);
    gat_edge_kernel<<<Nn, 256>>>(att0, b0, ln_g, ln_b, 0, 1);

    // layers 1..3 (K=1024 -> K3=3072)
    for (int i = 0; i < 3; i++) {
        int insel = (i & 1) ? 2 : 1;
        int outsel = (i & 1) ? 1 : 2;
        convA_kernel<<<(Nn * HC + 255) / 256, 256>>>(nullptr, insel, 10);
        gemm_mma_kernel<<<gg, 256, GEMM_SMEM>>>(OFF_WLi(i), bl + i * HC, 0, 3 * HC);
        gemm_mma_kernel<<<gg, 256, GEMM_SMEM>>>(OFF_WRi(i), br + i * HC, 1, 3 * HC);
        gat_edge_kernel<<<Nn, 256>>>(att + (size_t)i * Hh * Cc, b + i * HC,
                                     ln_g + (i + 1) * HC, ln_b + (i + 1) * HC,
                                     insel, outsel);
    }

    // mean pool + heads
    pool_zero_kernel<<<(Gg * HC + 255) / 256, 256>>>();
    pool_sum_kernel<<<(Nn * HC + 255) / 256, 256>>>(batch);
    pool_cnt_kernel<<<(Nn + 255) / 256, 256>>>(batch);
    head_kernel<<<Gg, 128>>>(y_type, Temb, W_fam, b_fam, W_type, b_type, out);
}

// round 8
// speedup vs baseline: 2.1561x; 1.0876x over previous
#include <cuda_runtime.h>
#include <cuda_bf16.h>
#include <cstdint>

#define Nn 8192
#define Ee 98304
#define ET (Ee + Nn)
#define Gg 64
#define INdim 128
#define Hh 8
#define Cc 128
#define HC 1024
#define TEdim 16
#define NTYPEc 32
#define NFAMc 64
#define SLOPE 0.2f
#define EPSc 1e-5f

// ---- GEMM tiling (mma.sync bf16, split-fp32 via K-concat x3) ---------------
#define BM 128
#define BN 128
#define BKc 32
#define ROWB 80                 // padded SMEM row stride in bytes (32 bf16 = 64B data)
#define STG 20480               // per-stage bytes: A 128*80 + B 128*80
#define NSTAGE 4
#define GEMM_SMEM (NSTAGE * STG)

// d_Wcat element offsets ([n][3K] bf16 per matrix; WL/WR adjacent -> 2048 rows)
#define BIGW 3145728            // 1024*3072
#define SMALLW 393216           // 1024*384
#define OFF_WL0 0
#define OFF_WR0 SMALLW
#define OFF_WB (2 * SMALLW)
#define OFF_WLi(i) (OFF_WB + (size_t)(i) * 2 * BIGW)
#define OFF_WRi(i) (OFF_WLi(i) + BIGW)
#define WT_ELEMS (OFF_WB + 6 * BIGW)
#define ACAT_ELEMS (Nn * 3072)

// ---------------- scratch (device globals; no allocation allowed) ----------
__device__ float d_XL[Nn * HC];
__device__ float d_XR[Nn * HC];
__device__ float d_H1[Nn * HC];
__device__ float d_H2[Nn * HC];
__device__ int   d_rowptr[Nn + 1];
__device__ int   d_colidx[ET];
__device__ int   d_cnt[Nn];
__device__ int   d_cur[Nn];
__device__ __nv_bfloat16 d_Acat[ACAT_ELEMS];
__device__ __nv_bfloat16 d_Wcat[WT_ELEMS];

// ---------------- PTX helpers ----------------------------------------------
__device__ __forceinline__ uint32_t smem_u32_of(const void* p) {
    uint32_t a;
    asm("{ .reg .u64 t; cvta.to.shared.u64 t, %1; cvt.u32.u64 %0, t; }" : "=r"(a) : "l"(p));
    return a;
}

#define CPA16(dst, src) \
    asm volatile("cp.async.cg.shared.global [%0], [%1], 16;" :: "r"(dst), "l"(src))

#define LDSMX4(r, addr) \
    asm volatile("ldmatrix.sync.aligned.m8n8.x4.shared.b16 {%0,%1,%2,%3}, [%4];" \
                 : "=r"((r)[0]), "=r"((r)[1]), "=r"((r)[2]), "=r"((r)[3]) : "r"(addr))

#define MMA16816(c, a, b0, b1) \
    asm volatile("mma.sync.aligned.m16n8k16.row.col.f32.bf16.bf16.f32 " \
                 "{%0,%1,%2,%3}, {%4,%5,%6,%7}, {%8,%9}, {%0,%1,%2,%3};" \
                 : "+f"((c)[0]), "+f"((c)[1]), "+f"((c)[2]), "+f"((c)[3]) \
                 : "r"((a)[0]), "r"((a)[1]), "r"((a)[2]), "r"((a)[3]), "r"(b0), "r"(b1))

// ---------------- CSR build ------------------------------------------------
__global__ void csr_zero_kernel() {
    int i = blockIdx.x * blockDim.x + threadIdx.x;
    if (i < Nn) { d_cnt[i] = 0; d_cur[i] = 0; }
}

__global__ void csr_count_kernel(const int* __restrict__ edge) {
    int i = blockIdx.x * blockDim.x + threadIdx.x;
    if (i < ET) {
        int dst = (i < Ee) ? edge[Ee + i] : (i - Ee);
        atomicAdd(&d_cnt[dst], 1);
    }
}

__global__ void csr_scan_kernel() {
    int tid = threadIdx.x;
    int base = tid * 8;
    int local[8];
    int s = 0;
#pragma unroll
    for (int j = 0; j < 8; j++) { local[j] = d_cnt[base + j]; s += local[j]; }
    __shared__ int ps[1024];
    ps[tid] = s;
    __syncthreads();
    for (int off = 1; off < 1024; off <<= 1) {
        int v = (tid >= off) ? ps[tid - off] : 0;
        __syncthreads();
        ps[tid] += v;
        __syncthreads();
    }
    int run = ps[tid] - s;
#pragma unroll
    for (int j = 0; j < 8; j++) { d_rowptr[base + j] = run; run += local[j]; }
    if (tid == 1023) d_rowptr[Nn] = run;
}

__global__ void csr_fill_kernel(const int* __restrict__ edge) {
    int i = blockIdx.x * blockDim.x + threadIdx.x;
    if (i < ET) {
        int src, dst;
        if (i < Ee) { src = edge[i]; dst = edge[Ee + i]; }
        else        { src = i - Ee;  dst = i - Ee; }
        int pos = d_rowptr[dst] + atomicAdd(&d_cur[dst], 1);
        d_colidx[pos] = src;
    }
}

// ---------------- fp32 -> split bf16, K-concat [hi | hi | lo] (layer0 only) -
__global__ void convA_kernel(const float* __restrict__ ext) {
    int i = blockIdx.x * blockDim.x + threadIdx.x;
    if (i < Nn * INdim) {
        float v = ext[i];
        __nv_bfloat16 h = __float2bfloat16(v);
        __nv_bfloat16 lo = __float2bfloat16(v - __bfloat162float(h));
        int r = i >> 7;
        int k = i & (INdim - 1);
        size_t o = (size_t)r * (3 * INdim) + k;
        d_Acat[o] = h;
        d_Acat[o + INdim] = h;
        d_Acat[o + 2 * INdim] = lo;
    }
}

// transpose [K,1024] -> [1024,3K] with [Bh | Bl | Bh] concat
__global__ void convW_kernel(const float* __restrict__ W, size_t outOff, int K) {
    __shared__ float t[32][33];
    int k0 = blockIdx.x * 32, n0 = blockIdx.y * 32;
    int tx = threadIdx.x, ty = threadIdx.y;
    for (int r = ty; r < 32; r += 8) t[r][tx] = W[(size_t)(k0 + r) * HC + n0 + tx];
    __syncthreads();
    for (int r = ty; r < 32; r += 8) {
        float v = t[tx][r];  // = W[k0+tx][n0+r]
        __nv_bfloat16 h = __float2bfloat16(v);
        __nv_bfloat16 lo = __float2bfloat16(v - __bfloat162float(h));
        size_t o = outOff + (size_t)(n0 + r) * (3 * K) + (k0 + tx);
        d_Wcat[o] = h;          // pairs with Ah
        d_Wcat[o + K] = lo;     // pairs with Ah
        d_Wcat[o + 2 * K] = h;  // pairs with Al
    }
}

// ---------------- fused mma.sync GEMM: [XL|XR] = Acat @ [WL;WR]^T + bias ----
// CTA 128x128, BK=32, 4-stage cp.async pipeline, warp grid 2(m) x 4(n).
// B has 2048 rows (WL rows 0..1023, WR rows 1024..2047).
__global__ __launch_bounds__(256) void gemm_mma_kernel(
    size_t wOff, const float* __restrict__ biasL, const float* __restrict__ biasR,
    int K3) {
    extern __shared__ __align__(128) char sm[];
    uint32_t su = smem_u32_of(sm);
    const __nv_bfloat16* __restrict__ Ag = d_Acat;
    const __nv_bfloat16* __restrict__ Bg = d_Wcat + wOff;

    int tid = threadIdx.x;
    int wid = tid >> 5, l = tid & 31;
    int wm = wid >> 2, wn = wid & 3;
    int row0 = blockIdx.y * BM, col0 = blockIdx.x * BN;   // col0 in [0,2048)

    int lr = tid >> 2;
    int chB = (tid & 3) * 16;
    int ch8 = (tid & 3) * 8;

    uint32_t aOff = (uint32_t)((wm * 64 + (l & 15)) * ROWB + (l >> 4) * 16);
    uint32_t bOff = (uint32_t)(BM * ROWB +
                               (wn * 32 + (l & 7) + ((l >> 4) << 3)) * ROWB +
                               ((l >> 3) & 1) * 16);

    float c[4][4][4];
#pragma unroll
    for (int a = 0; a < 4; a++)
#pragma unroll
        for (int b = 0; b < 4; b++)
#pragma unroll
            for (int d = 0; d < 4; d++) c[a][b][d] = 0.f;

    const int NT = K3 >> 5;

    // prologue: stages 0..NSTAGE-2
#pragma unroll
    for (int s = 0; s < NSTAGE - 1; s++) {
        uint32_t sb = su + s * STG;
        int k0 = s * BKc;
        CPA16(sb + lr * ROWB + chB,               Ag + (size_t)(row0 + lr) * K3 + k0 + ch8);
        CPA16(sb + (lr + 64) * ROWB + chB,        Ag + (size_t)(row0 + lr + 64) * K3 + k0 + ch8);
        CPA16(sb + BM * ROWB + lr * ROWB + chB,        Bg + (size_t)(col0 + lr) * K3 + k0 + ch8);
        CPA16(sb + BM * ROWB + (lr + 64) * ROWB + chB, Bg + (size_t)(col0 + lr + 64) * K3 + k0 + ch8);
        asm volatile("cp.async.commit_group;" ::: "memory");
    }

    for (int it = 0; it < NT; it++) {
        asm volatile("cp.async.wait_group %0;" :: "n"(NSTAGE - 2) : "memory");
        __syncthreads();

        // issue next-stage loads FIRST (slot (it+NSTAGE-1)%NSTAGE was consumed
        // at iter it-1; the barrier above makes the overwrite safe)
        int kn = (it + NSTAGE - 1) * BKc;
        if (kn < K3) {
            uint32_t sb2 = su + ((it + NSTAGE - 1) % NSTAGE) * STG;
            CPA16(sb2 + lr * ROWB + chB,               Ag + (size_t)(row0 + lr) * K3 + kn + ch8);
            CPA16(sb2 + (lr + 64) * ROWB + chB,        Ag + (size_t)(row0 + lr + 64) * K3 + kn + ch8);
            CPA16(sb2 + BM * ROWB + lr * ROWB + chB,        Bg + (size_t)(col0 + lr) * K3 + kn + ch8);
            CPA16(sb2 + BM * ROWB + (lr + 64) * ROWB + chB, Bg + (size_t)(col0 + lr + 64) * K3 + kn + ch8);
        }
        asm volatile("cp.async.commit_group;" ::: "memory");

        uint32_t sb = su + (it % NSTAGE) * STG;
#pragma unroll
        for (int kk = 0; kk < 2; kk++) {
            uint32_t av[4][4], bv[2][4];
#pragma unroll
            for (int mt = 0; mt < 4; mt++)
                LDSMX4(av[mt], sb + aOff + mt * (16 * ROWB) + kk * 32);
#pragma unroll
            for (int bt = 0; bt < 2; bt++)
                LDSMX4(bv[bt], sb + bOff + bt * (16 * ROWB) + kk * 32);
#pragma unroll
            for (int mt = 0; mt < 4; mt++) {
                MMA16816(c[mt][0], av[mt], bv[0][0], bv[0][1]);
                MMA16816(c[mt][1], av[mt], bv[0][2], bv[0][3]);
                MMA16816(c[mt][2], av[mt], bv[1][0], bv[1][1]);
                MMA16816(c[mt][3], av[mt], bv[1][2], bv[1][3]);
            }
        }
    }

    // epilogue
    int isR = (col0 >= HC);
    float* __restrict__ Cm = isR ? d_XR : d_XL;
    const float* __restrict__ bias = isR ? biasR : biasL;
    int colBase = col0 - (isR ? HC : 0);
    int mrow = l >> 2;
    int ncol = (l & 3) * 2;
#pragma unroll
    for (int mt = 0; mt < 4; mt++) {
#pragma unroll
        for (int nt = 0; nt < 4; nt++) {
            int row = row0 + wm * 64 + mt * 16 + mrow;
            int col = colBase + wn * 32 + nt * 8 + ncol;
            float b0 = bias[col], b1 = bias[col + 1];
            float2 v0 = make_float2(c[mt][nt][0] + b0, c[mt][nt][1] + b1);
            float2 v1 = make_float2(c[mt][nt][2] + b0, c[mt][nt][3] + b1);
            *(float2*)&Cm[(size_t)row * HC + col] = v0;
            *(float2*)&Cm[(size_t)(row + 8) * HC + col] = v1;
        }
    }
}

// ---------------- GATv2 agg + bias + ReLU + LN (+res) + bf16-split out -----
__global__ __launch_bounds__(256) void gat_edge_kernel(
    const float* __restrict__ att, const float* __restrict__ bias,
    const float* __restrict__ lng, const float* __restrict__ lnb,
    int res_sel, int out_sel, int writeA) {
    int n = blockIdx.x;
    int w = threadIdx.x >> 5;
    int l = threadIdx.x & 31;
    int c0 = w * Cc + l;

    const float* xr = d_XR + (size_t)n * HC;
    float xr0 = xr[c0], xr1 = xr[c0 + 32], xr2 = xr[c0 + 64], xr3 = xr[c0 + 96];
    const float* ah = att + w * Cc;
    float a0 = ah[l], a1 = ah[l + 32], a2 = ah[l + 64], a3 = ah[l + 96];

    float m = -3.0e38f, dsum = 0.f;
    float acc0 = 0.f, acc1 = 0.f, acc2 = 0.f, acc3 = 0.f;

    int beg = d_rowptr[n], end = d_rowptr[n + 1];
    for (int e = beg; e < end; e++) {
        int s = d_colidx[e];
        const float* xl = d_XL + (size_t)s * HC;
        float x0 = xl[c0], x1 = xl[c0 + 32], x2 = xl[c0 + 64], x3 = xl[c0 + 96];
        float t0 = x0 + xr0; t0 = (t0 > 0.f) ? t0 : SLOPE * t0;
        float t1 = x1 + xr1; t1 = (t1 > 0.f) ? t1 : SLOPE * t1;
        float t2 = x2 + xr2; t2 = (t2 > 0.f) ? t2 : SLOPE * t2;
        float t3 = x3 + xr3; t3 = (t3 > 0.f) ? t3 : SLOPE * t3;
        float p = a0 * t0 + a1 * t1 + a2 * t2 + a3 * t3;
#pragma unroll
        for (int off = 16; off; off >>= 1) p += __shfl_xor_sync(0xffffffffu, p, off);
        float mn = fmaxf(m, p);
        float sc = __expf(m - mn);
        float wg = __expf(p - mn);
        dsum = dsum * sc + wg;
        acc0 = acc0 * sc + x0 * wg;
        acc1 = acc1 * sc + x1 * wg;
        acc2 = acc2 * sc + x2 * wg;
        acc3 = acc3 * sc + x3 * wg;
        m = mn;
    }

    float inv = 1.f / dsum;
    float v0 = fmaxf(acc0 * inv + bias[c0],       0.f);
    float v1 = fmaxf(acc1 * inv + bias[c0 + 32],  0.f);
    float v2 = fmaxf(acc2 * inv + bias[c0 + 64],  0.f);
    float v3 = fmaxf(acc3 * inv + bias[c0 + 96],  0.f);

    float ps = v0 + v1 + v2 + v3;
    float pq = v0 * v0 + v1 * v1 + v2 * v2 + v3 * v3;
#pragma unroll
    for (int off = 16; off; off >>= 1) {
        ps += __shfl_xor_sync(0xffffffffu, ps, off);
        pq += __shfl_xor_sync(0xffffffffu, pq, off);
    }
    __shared__ float rs[8], rq[8];
    __shared__ float s_mu, s_rstd;
    if (l == 0) { rs[w] = ps; rq[w] = pq; }
    __syncthreads();
    if (threadIdx.x == 0) {
        float S = 0.f, Q = 0.f;
#pragma unroll
        for (int k = 0; k < 8; k++) { S += rs[k]; Q += rq[k]; }
        float mu = S * (1.f / HC);
        float var = Q * (1.f / HC) - mu * mu;
        s_mu = mu;
        s_rstd = rsqrtf(var + EPSc);
    }
    __syncthreads();
    float mu = s_mu, rstd = s_rstd;

    const float* res = (res_sel == 0) ? nullptr : ((res_sel == 1) ? d_H1 : d_H2);
    float* Ho = (out_sel == 1) ? d_H1 : d_H2;
    size_t o = (size_t)n * HC;
    float hv[4];
    int cs[4] = {c0, c0 + 32, c0 + 64, c0 + 96};
    float vv[4] = {v0, v1, v2, v3};
#pragma unroll
    for (int k = 0; k < 4; k++) {
        int cc = cs[k];
        float r = res ? res[o + cc] : 0.f;
        hv[k] = (vv[k] - mu) * rstd * lng[cc] + lnb[cc] + r;
        Ho[o + cc] = hv[k];
    }
    if (writeA) {
        size_t ao = (size_t)n * (3 * HC);
#pragma unroll
        for (int k = 0; k < 4; k++) {
            int cc = cs[k];
            __nv_bfloat16 h = __float2bfloat16(hv[k]);
            __nv_bfloat16 lo = __float2bfloat16(hv[k] - __bfloat162float(h));
            d_Acat[ao + cc] = h;
            d_Acat[ao + cc + HC] = h;
            d_Acat[ao + cc + 2 * HC] = lo;
        }
    }
}

// ---------------- fused mean-pool (sorted batch) + heads --------------------
__global__ void head_kernel(const int* __restrict__ batch,
                            const int* __restrict__ y_type,
                            const float* __restrict__ Temb,
                            const float* __restrict__ W_fam,
                            const float* __restrict__ b_fam,
                            const float* __restrict__ W_type,
                            const float* __restrict__ b_type,
                            float* __restrict__ out) {
    __shared__ float gf[HC + TEdim];
    __shared__ int s_s, s_e;
    int g = blockIdx.x;
    int tid = threadIdx.x;
    if (tid == 0) {
        int lo = 0, hi = Nn;
        while (lo < hi) { int mid = (lo + hi) >> 1; if (batch[mid] < g) lo = mid + 1; else hi = mid; }
        s_s = lo;
        lo = 0; hi = Nn;
        while (lo < hi) { int mid = (lo + hi) >> 1; if (batch[mid] < g + 1) lo = mid + 1; else hi = mid; }
        s_e = lo;
    }
    __syncthreads();
    int s = s_s, e = s_e;
    float acc[8] = {0.f, 0.f, 0.f, 0.f, 0.f, 0.f, 0.f, 0.f};
    for (int n = s; n < e; n++) {
        const float* hp = d_H2 + (size_t)n * HC;
#pragma unroll
        for (int k = 0; k < 8; k++) acc[k] += hp[tid + k * 128];
    }
    float invc = 1.f / fmaxf((float)(e - s), 1.f);
#pragma unroll
    for (int k = 0; k < 8; k++) gf[tid + k * 128] = acc[k] * invc;
    if (tid < TEdim) gf[HC + tid] = Temb[y_type[g] * TEdim + tid];
    __syncthreads();
    if (tid < NFAMc) {
        float sum = b_fam[tid];
        for (int c = 0; c < HC + TEdim; c++) sum += gf[c] * W_fam[c * NFAMc + tid];
        out[g * NFAMc + tid] = sum;
    } else if (tid < NFAMc + NTYPEc) {
        int j = tid - NFAMc;
        float sum = b_type[j];
        for (int c = 0; c < HC + TEdim; c++) sum += gf[c] * W_type[c * NTYPEc + j];
        out[Gg * NFAMc + g * NTYPEc + j] = sum;
    }
}

// ---------------- launch ----------------------------------------------------
extern "C" void kernel_launch(void* const* d_in, const int* in_sizes, int n_in,
                              void* d_out, int out_size) {
    const float* x      = (const float*)d_in[0];
    const int*   edge   = (const int*)d_in[1];
    const int*   batch  = (const int*)d_in[2];
    const int*   y_type = (const int*)d_in[3];
    const float* Wl0    = (const float*)d_in[4];
    const float* bl0    = (const float*)d_in[5];
    const float* Wr0    = (const float*)d_in[6];
    const float* br0    = (const float*)d_in[7];
    const float* att0   = (const float*)d_in[8];
    const float* b0     = (const float*)d_in[9];
    const float* Wl     = (const float*)d_in[10];
    const float* bl     = (const float*)d_in[11];
    const float* Wr     = (const float*)d_in[12];
    const float* br     = (const float*)d_in[13];
    const float* att    = (const float*)d_in[14];
    const float* b      = (const float*)d_in[15];
    const float* ln_g   = (const float*)d_in[16];
    const float* ln_b   = (const float*)d_in[17];
    const float* Temb   = (const float*)d_in[18];
    const float* W_fam  = (const float*)d_in[19];
    const float* b_fam  = (const float*)d_in[20];
    const float* W_type = (const float*)d_in[21];
    const float* b_type = (const float*)d_in[22];
    float* out = (float*)d_out;

    cudaFuncSetAttribute(gemm_mma_kernel,
                         cudaFuncAttributeMaxDynamicSharedMemorySize, GEMM_SMEM);

    // weight transpose + split + concat (per launch)
    dim3 wtb(32, 8);
    convW_kernel<<<dim3(4, 32), wtb>>>(Wl0, OFF_WL0, INdim);
    convW_kernel<<<dim3(4, 32), wtb>>>(Wr0, OFF_WR0, INdim);
    for (int i = 0; i < 3; i++) {
        convW_kernel<<<dim3(32, 32), wtb>>>(Wl + (size_t)i * HC * HC, OFF_WLi(i), HC);
        convW_kernel<<<dim3(32, 32), wtb>>>(Wr + (size_t)i * HC * HC, OFF_WRi(i), HC);
    }

    // CSR build
    csr_zero_kernel<<<(Nn + 255) / 256, 256>>>();
    csr_count_kernel<<<(ET + 255) / 256, 256>>>(edge);
    csr_scan_kernel<<<1, 1024>>>();
    csr_fill_kernel<<<(ET + 255) / 256, 256>>>(edge);

    dim3 gg(2 * HC / BN, Nn / BM);  // (16, 64): XL and XR in one launch

    // layer 0 (K3 = 384)
    convA_kernel<<<(Nn * INdim + 255) / 256, 256>>>(x);
    gemm_mma_kernel<<<gg, 256, GEMM_SMEM>>>(OFF_WL0, bl0, br0, 3 * INdim);
    gat_edge_kernel<<<Nn, 256>>>(att0, b0, ln_g, ln_b, 0, 1, 1);

    // layers 1..3 (K3 = 3072)
    for (int i = 0; i < 3; i++) {
        int insel = (i & 1) ? 2 : 1;
        int outsel = (i & 1) ? 1 : 2;
        gemm_mma_kernel<<<gg, 256, GEMM_SMEM>>>(OFF_WLi(i), bl + i * HC, br + i * HC, 3 * HC);
        gat_edge_kernel<<<Nn, 256>>>(att + (size_t)i * Hh * Cc, b + i * HC,
                                     ln_g + (i + 1) * HC, ln_b + (i + 1) * HC,
                                     insel, outsel, (i < 2) ? 1 : 0);
    }

    // fused mean-pool + heads
    head_kernel<<<Gg, 128>>>(batch, y_type, Temb, W_fam, b_fam, W_type, b_type, out);
}